// round 17
// baseline (speedup 1.0000x reference)
#include <cuda_runtime.h>
#include <cuda_bf16.h>
#include <cstdint>

// out = feat @ Wv + bv
//
// The reference's softmax over axis=-2 (j) followed by einsum('ijk,ik->ik')
// (a sum over j) makes the attention-weight branch sum to exactly 1 per
// (i,k), so out[i,k] == v[i,k] == (feat @ Wv + bv)[i,k].
//
// feat: [N=1024, C=256] f32   (d_in[0])
// Wv:   [C, C]          f32   (d_in[9])
// bv:   [C]             f32   (d_in[10])
// out:  [N, C]          f32
//
// Split precision on tensor cores (tcgen05 rejected by compute_103):
//   x ~= hi + lo (bf16);  A*B ~= Ah*Bh + Ah*Bl + Al*Bh   (fp32 accum)
// R17: R12's 64x32 tile + fragment maps, with K pipelined in 4 chunks of 64:
// LDG chunk c+1 (regs) -> MMA chunk c (smem) -> cvt+STS chunk c+1 -> sync.
// Only chunk 0's fill latency is exposed, attacking the serial
// fill->sync->MMA structure that R16 proved is the binder.

namespace {

constexpr int Cdim = 256;
constexpr int KC   = 64;    // k per chunk
constexpr int NCH  = 4;     // chunks

// chunked smem strides (ldmatrix conflict-free):
//  A rows: 64 bf16 = 128 B + 16 pad = 144 B (36 words = 4-bank shift/row)
//  B rows: 32 bf16 = 64 B + 16 pad = 80 B (validated since R12)
constexpr uint32_t A_STRIDE_B = 144;
constexpr uint32_t B_STRIDE_B = 80;
constexpr uint32_t A_BUF_B = 64 * A_STRIDE_B;        // 9216
constexpr uint32_t B_BUF_B = 64 * B_STRIDE_B;        // 5120
constexpr uint32_t SM_AHI  = 0;                      // [2][A_BUF_B]
constexpr uint32_t SM_ALO  = SM_AHI + 2 * A_BUF_B;   // 18432
constexpr uint32_t SM_BHI  = SM_ALO + 2 * A_BUF_B;   // 36864
constexpr uint32_t SM_BLO  = SM_BHI + 2 * B_BUF_B;   // 47104
constexpr uint32_t SM_BIAS = SM_BLO + 2 * B_BUF_B;   // 57344
constexpr uint32_t SMEM_BYTES = SM_BIAS + 128;       // 57472

#define LDSM_X4(r0, r1, r2, r3, addr)                                        \
    asm volatile("ldmatrix.sync.aligned.m8n8.x4.shared.b16 {%0,%1,%2,%3}, [%4];" \
                 : "=r"(r0), "=r"(r1), "=r"(r2), "=r"(r3) : "r"(addr))

#define LDSM_X2T(r0, r1, addr)                                               \
    asm volatile("ldmatrix.sync.aligned.m8n8.x2.trans.shared.b16 {%0,%1}, [%2];" \
                 : "=r"(r0), "=r"(r1) : "r"(addr))

#define MMA_BF16(c, a0, a1, a2, a3, b0, b1)                                  \
    asm volatile("mma.sync.aligned.m16n8k16.row.col.f32.bf16.bf16.f32 "      \
                 "{%0,%1,%2,%3}, {%4,%5,%6,%7}, {%8,%9}, {%0,%1,%2,%3};"     \
                 : "+f"((c)[0]), "+f"((c)[1]), "+f"((c)[2]), "+f"((c)[3])    \
                 : "r"(a0), "r"(a1), "r"(a2), "r"(a3), "r"(b0), "r"(b1))

__device__ __forceinline__ uint32_t smem_u32(const void* p) {
    uint32_t a;
    asm("{ .reg .u64 t; cvta.to.shared.u64 t, %1; cvt.u32.u64 %0, t; }"
        : "=r"(a) : "l"(p));
    return a;
}

__device__ __forceinline__ uint32_t pack_bf2(float a, float b) {
    uint32_t r;
    asm("cvt.rn.bf16x2.f32 %0, %1, %2;" : "=r"(r) : "f"(b), "f"(a));
    return r;
}
__device__ __forceinline__ void split4(float4 f, uint2& hi, uint2& lo) {
    hi.x = pack_bf2(f.x, f.y);
    hi.y = pack_bf2(f.z, f.w);
    const float hx = __uint_as_float(hi.x << 16);
    const float hy = __uint_as_float(hi.x & 0xFFFF0000u);
    const float hz = __uint_as_float(hi.y << 16);
    const float hw = __uint_as_float(hi.y & 0xFFFF0000u);
    lo.x = pack_bf2(f.x - hx, f.y - hy);
    lo.y = pack_bf2(f.z - hz, f.w - hw);
}

// CTA: 64(M) x 32(N), K pipelined in 4x64 chunks. 256 threads = 8 warps.
// Warp w: m-strip (w>>1)*16, column-half (w&1). Grid (8,16) = 128 CTAs.

__global__ __launch_bounds__(256, 1)
void vgemm_mma_kernel(const float* __restrict__ feat,  // [1024, 256]
                      const float* __restrict__ Wv,    // [256, 256]
                      const float* __restrict__ bias,  // [256]
                      float* __restrict__ O)           // [1024, 256]
{
    extern __shared__ char smem[];
    const uint32_t sb = smem_u32(smem);

    const int tid  = (int)threadIdx.x;   // 0..255
    const int warp = tid >> 5;
    const int lane = tid & 31;
    const int row0 = (int)blockIdx.y * 64;
    const int col0 = (int)blockIdx.x * 32;

    // per-thread fill coordinates
    const int am  = tid >> 4;            // A: base row 0..15 (+16*i)
    const int ac4 = tid & 15;            // A: float4 within 64-k row slice
    const int bk  = tid >> 3;            // B: base k-row 0..31 (+32*i)
    const int bc4 = tid & 7;             // B: float4 within 32-col row

    // ---- register-staged chunk loaders ----
    float4 ra[4];   // A chunk: 64 rows x 16 f4 = 1024 f4 -> 4 per thread
    float4 rb[2];   // B chunk: 64 k x 8 f4 = 512 f4 -> 2 per thread
    auto ldg_chunk = [&](int kk) {
        #pragma unroll
        for (int i = 0; i < 4; i++) {
            const int m = (i << 4) + am;
            ra[i] = *reinterpret_cast<const float4*>(
                &feat[(row0 + m) * Cdim + kk + ac4 * 4]);
        }
        #pragma unroll
        for (int i = 0; i < 2; i++) {
            const int k = (i << 5) + bk;
            rb[i] = *reinterpret_cast<const float4*>(
                &Wv[(kk + k) * Cdim + col0 + bc4 * 4]);
        }
    };
    auto store_chunk = [&](int buf) {
        #pragma unroll
        for (int i = 0; i < 4; i++) {
            const int m = (i << 4) + am;
            uint2 hi, lo;
            split4(ra[i], hi, lo);
            const uint32_t off = (uint32_t)buf * A_BUF_B +
                                 (uint32_t)m * A_STRIDE_B + (uint32_t)ac4 * 8;
            *reinterpret_cast<uint2*>(smem + SM_AHI + off) = hi;
            *reinterpret_cast<uint2*>(smem + SM_ALO + off) = lo;
        }
        #pragma unroll
        for (int i = 0; i < 2; i++) {
            const int k = (i << 5) + bk;
            uint2 hi, lo;
            split4(rb[i], hi, lo);
            const uint32_t off = (uint32_t)buf * B_BUF_B +
                                 (uint32_t)k * B_STRIDE_B + (uint32_t)bc4 * 8;
            *reinterpret_cast<uint2*>(smem + SM_BHI + off) = hi;
            *reinterpret_cast<uint2*>(smem + SM_BLO + off) = lo;
        }
    };

    float acc[2][4];
    #pragma unroll
    for (int t = 0; t < 2; t++)
        #pragma unroll
        for (int i = 0; i < 4; i++) acc[t][i] = 0.f;

    // stage bias
    if (tid < 8) {
        reinterpret_cast<float4*>(smem + SM_BIAS)[tid] =
            reinterpret_cast<const float4*>(bias + col0)[tid];
    }

    // ---- prologue: fill chunk 0 ----
    ldg_chunk(0);
    store_chunk(0);
    __syncthreads();

    // ---- mainloop fragment bases ----
    const int m0 = (warp >> 1) * 16;
    const int nh = (warp & 1) * 32;      // byte offset of 16-col half
    const uint32_t aRowOff =
        (uint32_t)(m0 + (lane & 15)) * A_STRIDE_B + (uint32_t)(lane >> 4) * 16;
    const uint32_t bRowOff = (uint32_t)(lane & 15) * B_STRIDE_B + (uint32_t)nh;

    #pragma unroll
    for (int c = 0; c < NCH; c++) {
        const int buf = c & 1;

        if (c + 1 < NCH)
            ldg_chunk((c + 1) * KC);     // latency hides under MMA below

        const uint32_t aHiBase = sb + SM_AHI + (uint32_t)buf * A_BUF_B + aRowOff;
        const uint32_t aLoBase = aHiBase + (SM_ALO - SM_AHI);
        const uint32_t bHiBase = sb + SM_BHI + (uint32_t)buf * B_BUF_B + bRowOff;

        #pragma unroll
        for (int ks = 0; ks < 4; ks++) {
            uint32_t ah0, ah1, ah2, ah3, al0, al1, al2, al3;
            LDSM_X4(ah0, ah1, ah2, ah3, aHiBase + (uint32_t)ks * 32);
            LDSM_X4(al0, al1, al2, al3, aLoBase + (uint32_t)ks * 32);

            const uint32_t bkA = bHiBase + (uint32_t)ks * (16 * B_STRIDE_B);
            #pragma unroll
            for (int t = 0; t < 2; t++) {
                uint32_t bh0, bh1, bl0, bl1;
                const uint32_t ba = bkA + (uint32_t)t * 16;
                LDSM_X2T(bh0, bh1, ba);
                LDSM_X2T(bl0, bl1, ba + (SM_BLO - SM_BHI));
                MMA_BF16(acc[t], ah0, ah1, ah2, ah3, bh0, bh1);
                MMA_BF16(acc[t], ah0, ah1, ah2, ah3, bl0, bl1);
                MMA_BF16(acc[t], al0, al1, al2, al3, bh0, bh1);
            }
        }

        if (c + 1 < NCH)
            store_chunk(buf ^ 1);
        __syncthreads();
    }

    // ---- epilogue: bias add + stores (canonical m16n8 D mapping) ----
    const float* bs = reinterpret_cast<const float*>(smem + SM_BIAS);
    const int g  = lane >> 2;
    const int tc = (lane & 3) * 2;
    const int r1 = row0 + m0 + g;
    const int r2 = r1 + 8;
    const int nb = (warp & 1) * 16;
    #pragma unroll
    for (int t = 0; t < 2; t++) {
        const int n = nb + t * 8 + tc;
        float2 o1, o2;
        o1.x = acc[t][0] + bs[n];
        o1.y = acc[t][1] + bs[n + 1];
        o2.x = acc[t][2] + bs[n];
        o2.y = acc[t][3] + bs[n + 1];
        *reinterpret_cast<float2*>(&O[r1 * Cdim + col0 + n]) = o1;
        *reinterpret_cast<float2*>(&O[r2 * Cdim + col0 + n]) = o2;
    }
}

} // namespace

extern "C" void kernel_launch(void* const* d_in, const int* in_sizes, int n_in,
                              void* d_out, int out_size)
{
    const float* feat = (const float*)d_in[0];
    const float* Wv   = (const float*)d_in[9];
    const float* bv   = (const float*)d_in[10];
    float* out        = (float*)d_out;

    cudaFuncSetAttribute(vgemm_mma_kernel,
                         cudaFuncAttributeMaxDynamicSharedMemorySize,
                         (int)SMEM_BYTES);
    dim3 grid(8, 16);   // 8 N-tiles x 16 M-tiles = 128 CTAs, one wave
    vgemm_mma_kernel<<<grid, 256, SMEM_BYTES>>>(feat, Wv, bv, out);
}